// round 5
// baseline (speedup 1.0000x reference)
#include <cuda_runtime.h>
#include <cstdint>

// Haar IDWT2: out[2i,2j]=(LL+LH+HL+HH)/2, out[2i,2j+1]=(LL+LH-HL-HH)/2,
//             out[2i+1,2j]=(LL-LH+HL-HH)/2, out[2i+1,2j+1]=(LL-LH-HL+HH)/2
// Shapes: inputs [B,C,H2,W2] = [16,64,128,128] fp32; output [B,C,256,256] fp32.
//
// R4: 2 rows x 2 cols (4 coeffs) per thread. 8 independent float2 loads +
// 4 float4 stores, all warp-contiguous (same coalescing as R1, 2x MLP).
// Streaming cache hints (__ldcs/__stcs): single-touch data, evict-first.

static constexpr int Bdim = 16;
static constexpr int Cdim = 64;
static constexpr int H2   = 128;
static constexpr int W2   = 128;
static constexpr int W2V2 = W2 / 2;              // float2 groups per input row = 64
static constexpr long long NCOEF = (long long)Bdim * Cdim * H2 * W2;   // 16,777,216
static constexpr int NTHREADS_TOTAL = (int)(NCOEF / 4);                // 4,194,304

__device__ __forceinline__ void haar_pair(float2 ll, float2 lh, float2 hl, float2 hh,
                                          float4& top, float4& bot)
{
    float s0 = ll.x + lh.x, t0 = ll.x - lh.x;
    float u0 = hl.x + hh.x, v0 = hl.x - hh.x;
    float s1 = ll.y + lh.y, t1 = ll.y - lh.y;
    float u1 = hl.y + hh.y, v1 = hl.y - hh.y;
    top = make_float4((s0 + u0) * 0.5f, (s0 - u0) * 0.5f,
                      (s1 + u1) * 0.5f, (s1 - u1) * 0.5f);
    bot = make_float4((t0 + v0) * 0.5f, (t0 - v0) * 0.5f,
                      (t1 + v1) * 0.5f, (t1 - v1) * 0.5f);
}

__global__ __launch_bounds__(256)
void idwt_haar_kernel(const float2* __restrict__ LL2,
                      const float2* __restrict__ LH2,
                      const float2* __restrict__ HL2,
                      const float2* __restrict__ HH2,
                      float* __restrict__ out)
{
    int tid = blockIdx.x * blockDim.x + threadIdx.x;
    int col2 = tid & (W2V2 - 1);         // 0..63
    int row2 = tid >> 6;                 // coefficient row PAIR index
    int row  = row2 * 2;                 // first coefficient row of the pair

    long long in_off0 = (long long)row * W2V2 + col2;
    long long in_off1 = in_off0 + W2V2;

    // 8 independent streaming loads (max MLP before any arithmetic)
    float2 ll0 = __ldcs(&LL2[in_off0]);
    float2 lh0 = __ldcs(&LH2[in_off0]);
    float2 hl0 = __ldcs(&HL2[in_off0]);
    float2 hh0 = __ldcs(&HH2[in_off0]);
    float2 ll1 = __ldcs(&LL2[in_off1]);
    float2 lh1 = __ldcs(&LH2[in_off1]);
    float2 hl1 = __ldcs(&HL2[in_off1]);
    float2 hh1 = __ldcs(&HH2[in_off1]);

    float4 t0, b0, t1, b1;
    haar_pair(ll0, lh0, hl0, hh0, t0, b0);
    haar_pair(ll1, lh1, hl1, hh1, t1, b1);

    // output addressing: image bc, coeff rows (row, row+1) -> out rows 2row..2row+3
    int bc = row >> 7;                   // row / H2 (pair never crosses image: H2 even)
    int i  = row & (H2 - 1);
    const int OW = 2 * W2;               // 256
    long long obase = ((long long)bc * (2 * H2) + 2 * i) * OW + (long long)col2 * 4;

    __stcs(reinterpret_cast<float4*>(out + obase),          t0);
    __stcs(reinterpret_cast<float4*>(out + obase + OW),     b0);
    __stcs(reinterpret_cast<float4*>(out + obase + 2 * OW), t1);
    __stcs(reinterpret_cast<float4*>(out + obase + 3 * OW), b1);
}

extern "C" void kernel_launch(void* const* d_in, const int* in_sizes, int n_in,
                              void* d_out, int out_size)
{
    const float2* LL = (const float2*)d_in[0];
    const float2* LH = (const float2*)d_in[1];
    const float2* HL = (const float2*)d_in[2];
    const float2* HH = (const float2*)d_in[3];
    float* out = (float*)d_out;

    const int threads = 256;
    const int blocks = NTHREADS_TOTAL / threads;   // 16384
    idwt_haar_kernel<<<blocks, threads>>>(LL, LH, HL, HH, out);
}

// round 7
// speedup vs baseline: 1.0287x; 1.0287x over previous
#include <cuda_runtime.h>
#include <cstdint>

// Haar IDWT2: out[2i,2j]=(LL+LH+HL+HH)/2, out[2i,2j+1]=(LL+LH-HL-HH)/2,
//             out[2i+1,2j]=(LL-LH+HL-HH)/2, out[2i+1,2j+1]=(LL-LH-HL+HH)/2
// Shapes: inputs [B,C,H2,W2] = [16,64,128,128] fp32; output [B,C,256,256] fp32.
//
// R5: best-known R1 structure (2 coeffs/thread, 16 regs, minimal-wavefront
// coalescing on both sides), block=512, plain cached loads + plain stores
// (streaming hints measured slightly worse). DRAM-bound at ~82% of spec;
// this round targets bus efficiency margins only.

static constexpr int Bdim = 16;
static constexpr int Cdim = 64;
static constexpr int H2   = 128;
static constexpr int W2   = 128;
static constexpr int W2V2 = W2 / 2;              // float2 groups per input row = 64
static constexpr long long NCOEF = (long long)Bdim * Cdim * H2 * W2;   // 16,777,216
static constexpr int NTHREADS_TOTAL = (int)(NCOEF / 2);                // 8,388,608

__global__ __launch_bounds__(512)
void idwt_haar_kernel(const float2* __restrict__ LL2,
                      const float2* __restrict__ LH2,
                      const float2* __restrict__ HL2,
                      const float2* __restrict__ HH2,
                      float* __restrict__ out)
{
    int tid = blockIdx.x * blockDim.x + threadIdx.x;
    int col2 = tid & (W2V2 - 1);         // 0..63
    int row  = tid >> 6;                 // global coefficient row index

    long long in_off = (long long)row * W2V2 + col2;
    float2 ll = __ldg(&LL2[in_off]);
    float2 lh = __ldg(&LH2[in_off]);
    float2 hl = __ldg(&HL2[in_off]);
    float2 hh = __ldg(&HH2[in_off]);

    // butterflies (x0.5)
    float s0 = ll.x + lh.x, t0 = ll.x - lh.x;
    float u0 = hl.x + hh.x, v0 = hl.x - hh.x;
    float a0 = (s0 + u0) * 0.5f;
    float b0 = (s0 - u0) * 0.5f;
    float c0 = (t0 + v0) * 0.5f;
    float d0 = (t0 - v0) * 0.5f;

    float s1 = ll.y + lh.y, t1 = ll.y - lh.y;
    float u1 = hl.y + hh.y, v1 = hl.y - hh.y;
    float a1 = (s1 + u1) * 0.5f;
    float b1 = (s1 - u1) * 0.5f;
    float c1 = (t1 + v1) * 0.5f;
    float d1 = (t1 - v1) * 0.5f;

    // output addressing
    int bc = row >> 7;                   // row / H2
    int i  = row & (H2 - 1);
    const int OW = 2 * W2;               // 256
    long long obase = ((long long)bc * (2 * H2) + 2 * i) * OW + (long long)col2 * 4;

    *reinterpret_cast<float4*>(out + obase)      = make_float4(a0, b0, a1, b1);
    *reinterpret_cast<float4*>(out + obase + OW) = make_float4(c0, d0, c1, d1);
}

extern "C" void kernel_launch(void* const* d_in, const int* in_sizes, int n_in,
                              void* d_out, int out_size)
{
    const float2* LL = (const float2*)d_in[0];
    const float2* LH = (const float2*)d_in[1];
    const float2* HL = (const float2*)d_in[2];
    const float2* HH = (const float2*)d_in[3];
    float* out = (float*)d_out;

    const int threads = 512;
    const int blocks = NTHREADS_TOTAL / threads;   // 16384
    idwt_haar_kernel<<<blocks, threads>>>(LL, LH, HL, HH, out);
}